// round 1
// baseline (speedup 1.0000x reference)
#include <cuda_runtime.h>

#define D   128        // feature dim (in == out == 128 for this problem)
#define KN  32         // neighbors per node
#define WPB 4          // warps (= nodes) per block
#define THREADS (WPB * 32)

__device__ float g_v[D];   // v = feat_weights @ attn_weights

// ---------------- prep: v[j] = sum_d W[j][d] * a[d] ----------------
__global__ void prep_kernel(const float* __restrict__ W,
                            const float* __restrict__ a) {
    int j = threadIdx.x;
    float s = 0.f;
#pragma unroll 8
    for (int d = 0; d < D; d++) s = fmaf(W[j * D + d], a[d], s);
    g_v[j] = s;
}

__device__ __forceinline__ float warpSum(float x) {
#pragma unroll
    for (int o = 16; o; o >>= 1) x += __shfl_xor_sync(0xffffffffu, x, o);
    return x;
}
__device__ __forceinline__ float warpMax(float x) {
#pragma unroll
    for (int o = 16; o; o >>= 1) x = fmaxf(x, __shfl_xor_sync(0xffffffffu, x, o));
    return x;
}

// ---------------- fused attention + aggregate + output GEMM ----------------
__global__ void __launch_bounds__(THREADS, 1)
gat_kernel(const float* __restrict__ self_vecs,
           const float* __restrict__ neigh,
           const float* __restrict__ W,
           const float* __restrict__ bias,
           float* __restrict__ out,
           int n_nodes) {
    __shared__ float s_tile[WPB][D];           // (self + agg) per node slot
    __shared__ float red[WPB][WPB][D];         // GEMM partials [jwarp][node][dim]

    const int warp = threadIdx.x >> 5;
    const int lane = threadIdx.x & 31;
    const int node = blockIdx.x * WPB + warp;

    if (node < n_nodes) {
        // v fragment + self row (lane l owns dims 4l..4l+3)
        const float4 v4 = reinterpret_cast<const float4*>(g_v)[lane];
        const float4 sv = __ldcs(reinterpret_cast<const float4*>(
                              self_vecs + (size_t)node * D) + lane);
        const float self_logit =
            warpSum(fmaf(sv.x, v4.x, fmaf(sv.y, v4.y, fmaf(sv.z, v4.z, sv.w * v4.w))));

        // stream all 32 neighbor rows into registers (coalesced, evict-first)
        const float4* np = reinterpret_cast<const float4*>(
            neigh + (size_t)node * KN * D);
        float4 r[KN];
#pragma unroll
        for (int k = 0; k < KN; k++) r[k] = __ldcs(np + k * (D / 4) + lane);

        // per-lane partial dot products for all 32 neighbors
        float a_[KN];
#pragma unroll
        for (int k = 0; k < KN; k++)
            a_[k] = fmaf(r[k].x, v4.x,
                    fmaf(r[k].y, v4.y,
                    fmaf(r[k].z, v4.z, r[k].w * v4.w)));

        // butterfly multi-reduce: 31 shfls -> lane l holds full logit for k==l
#pragma unroll
        for (int off = 16; off > 0; off >>= 1) {
            const bool hi = (lane & off);
#pragma unroll
            for (int i = 0; i < off; i++) {
                float mine = hi ? a_[i + off] : a_[i];
                float send = hi ? a_[i]       : a_[i + off];
                float recv = __shfl_xor_sync(0xffffffffu, send, off);
                a_[i] = mine + recv;
            }
        }

        // leaky_relu + softmax over the 32 lanes (k == lane)
        float x = a_[0] + self_logit;
        x = (x > 0.f) ? x : 0.2f * x;
        const float m   = warpMax(x);
        const float e   = __expf(x - m);
        const float inv = 1.0f / warpSum(e);
        const float coef = e * inv;

        // weighted aggregate in INPUT space; start from self vec
        float4 acc = sv;
#pragma unroll
        for (int k = 0; k < KN; k++) {
            const float c = __shfl_sync(0xffffffffu, coef, k);
            acc.x = fmaf(c, r[k].x, acc.x);
            acc.y = fmaf(c, r[k].y, acc.y);
            acc.z = fmaf(c, r[k].z, acc.z);
            acc.w = fmaf(c, r[k].w, acc.w);
        }
        reinterpret_cast<float4*>(&s_tile[warp][0])[lane] = acc;
    }
    __syncthreads();

    // ---- output GEMM: out[n][d] = relu(sum_j s[n][j]*W[j][d] + bias[d]) ----
    // j-split across warps so W is read ONCE per block (amortized over WPB nodes)
    {
        float4 accb[WPB];
#pragma unroll
        for (int nn = 0; nn < WPB; nn++) accb[nn] = make_float4(0.f, 0.f, 0.f, 0.f);

        const float4* Wv = reinterpret_cast<const float4*>(W);
        const int jbase = warp * (D / WPB);
#pragma unroll 8
        for (int jj = 0; jj < D / WPB; jj++) {
            const int j = jbase + jj;
            const float4 wj = Wv[j * (D / 4) + lane];
#pragma unroll
            for (int nn = 0; nn < WPB; nn++) {
                const float sj = s_tile[nn][j];
                accb[nn].x = fmaf(sj, wj.x, accb[nn].x);
                accb[nn].y = fmaf(sj, wj.y, accb[nn].y);
                accb[nn].z = fmaf(sj, wj.z, accb[nn].z);
                accb[nn].w = fmaf(sj, wj.w, accb[nn].w);
            }
        }
#pragma unroll
        for (int nn = 0; nn < WPB; nn++)
            reinterpret_cast<float4*>(&red[warp][nn][0])[lane] = accb[nn];
    }
    __syncthreads();

    // final reduce: warp nn owns node slot nn
    {
        const int nn = warp;
        const int node2 = blockIdx.x * WPB + nn;
        if (node2 < n_nodes) {
            float4 t = make_float4(0.f, 0.f, 0.f, 0.f);
#pragma unroll
            for (int w2 = 0; w2 < WPB; w2++) {
                const float4 p = reinterpret_cast<const float4*>(&red[w2][nn][0])[lane];
                t.x += p.x; t.y += p.y; t.z += p.z; t.w += p.w;
            }
            const float4 b4 = reinterpret_cast<const float4*>(bias)[lane];
            t.x = fmaxf(t.x + b4.x, 0.f);
            t.y = fmaxf(t.y + b4.y, 0.f);
            t.z = fmaxf(t.z + b4.z, 0.f);
            t.w = fmaxf(t.w + b4.w, 0.f);
            reinterpret_cast<float4*>(out + (size_t)node2 * D)[lane] = t;
        }
    }
}

extern "C" void kernel_launch(void* const* d_in, const int* in_sizes, int n_in,
                              void* d_out, int out_size) {
    const float* self_vecs = (const float*)d_in[0];
    const float* neigh     = (const float*)d_in[1];
    const float* W         = (const float*)d_in[2];
    const float* attn      = (const float*)d_in[3];
    const float* bias      = (const float*)d_in[4];
    float* out = (float*)d_out;

    const int n = in_sizes[0] / D;

    prep_kernel<<<1, D>>>(W, attn);
    const int blocks = (n + WPB - 1) / WPB;
    gat_kernel<<<blocks, THREADS>>>(self_vecs, neigh, W, bias, out, n);
}